// round 2
// baseline (speedup 1.0000x reference)
#include <cuda_runtime.h>
#include <cuda_bf16.h>
#include <cstdint>
#include <math.h>

// ---------------- problem constants ----------------
#define HID  2048
#define DFF  8192
#define NEXP 8
#define NTOK 8192            // B*S = 4*2048
#define SLOTS (2*NTOK)       // top-2 => 16384 token-expert slots

// ---------------- device scratch (no allocs allowed) ----------------
__device__ int   g_count[NEXP];
__device__ int   g_offset[NEXP];
__device__ int   g_tok_idx[2*NTOK];     // per-token top2 expert ids
__device__ float g_tok_w[2*NTOK];       // per-token top2 weights
__device__ int   g_list_token[SLOTS];   // compacted per-expert token lists
__device__ float g_list_w[SLOTS];
__device__ float g_hmid[(size_t)SLOTS * DFF];   // 512 MB fp32 intermediate

// ---------------- helpers ----------------
__device__ __forceinline__ uint32_t f2tf(float f) {
    uint32_t r;
    asm("cvt.rna.tf32.f32 %0, %1;" : "=r"(r) : "f"(f));
    return r;
}

__device__ __forceinline__ void mma_tf32(float c[4],
                                         uint32_t a0, uint32_t a1, uint32_t a2, uint32_t a3,
                                         uint32_t b0, uint32_t b1) {
    asm volatile(
        "mma.sync.aligned.m16n8k8.row.col.f32.tf32.tf32.f32 "
        "{%0,%1,%2,%3}, {%4,%5,%6,%7}, {%8,%9}, {%0,%1,%2,%3};\n"
        : "+f"(c[0]), "+f"(c[1]), "+f"(c[2]), "+f"(c[3])
        : "r"(a0), "r"(a1), "r"(a2), "r"(a3), "r"(b0), "r"(b1));
}

__device__ __forceinline__ float gelu_f(float v) {
    // jax.nn.gelu approximate=True (tanh form)
    float v3 = v * v * v;
    return 0.5f * v * (1.0f + tanhf(0.7978845608028654f * (v + 0.044715f * v3)));
}

// ---------------- kernel 0: init ----------------
__global__ void init_kernel(float* __restrict__ out) {
    size_t n4 = (size_t)NTOK * HID / 4;
    size_t stride = (size_t)gridDim.x * blockDim.x;
    float4 z = make_float4(0.f, 0.f, 0.f, 0.f);
    for (size_t i = (size_t)blockIdx.x * blockDim.x + threadIdx.x; i < n4; i += stride)
        reinterpret_cast<float4*>(out)[i] = z;
    if (blockIdx.x == 0 && threadIdx.x < NEXP) g_count[threadIdx.x] = 0;
}

// ---------------- kernel 1: router ----------------
// one warp per token: logits = x[t] @ w_gate, softmax fp32, top-2
__global__ void router_kernel(const float* __restrict__ x,
                              const float* __restrict__ wg,
                              float* __restrict__ logits_out) {
    int warp = threadIdx.x >> 5;
    int lane = threadIdx.x & 31;
    int t = blockIdx.x * 8 + warp;
    if (t >= NTOK) return;

    const float* xr = x + (size_t)t * HID;
    float acc[NEXP];
#pragma unroll
    for (int e = 0; e < NEXP; e++) acc[e] = 0.f;

    for (int h = lane; h < HID; h += 32) {
        float xv = xr[h];
        float4 g0 = *reinterpret_cast<const float4*>(wg + (size_t)h * NEXP);
        float4 g1 = *reinterpret_cast<const float4*>(wg + (size_t)h * NEXP + 4);
        acc[0] += xv * g0.x; acc[1] += xv * g0.y; acc[2] += xv * g0.z; acc[3] += xv * g0.w;
        acc[4] += xv * g1.x; acc[5] += xv * g1.y; acc[6] += xv * g1.z; acc[7] += xv * g1.w;
    }
#pragma unroll
    for (int e = 0; e < NEXP; e++)
#pragma unroll
        for (int s = 16; s > 0; s >>= 1)
            acc[e] += __shfl_xor_sync(0xffffffffu, acc[e], s);

    if (lane == 0) {
        float mx = acc[0];
#pragma unroll
        for (int e = 1; e < NEXP; e++) mx = fmaxf(mx, acc[e]);
        float p[NEXP];
        float s = 0.f;
#pragma unroll
        for (int e = 0; e < NEXP; e++) { p[e] = expf(acc[e] - mx); s += p[e]; }
        float inv = 1.f / s;
#pragma unroll
        for (int e = 0; e < NEXP; e++) p[e] *= inv;

        int i0 = 0;
#pragma unroll
        for (int e = 1; e < NEXP; e++) if (p[e] > p[i0]) i0 = e;
        int i1 = (i0 == 0) ? 1 : 0;
#pragma unroll
        for (int e = 0; e < NEXP; e++) if (e != i0 && p[e] > p[i1]) i1 = e;

        g_tok_idx[2*t+0] = i0; g_tok_idx[2*t+1] = i1;
        g_tok_w[2*t+0] = p[i0]; g_tok_w[2*t+1] = p[i1];
        atomicAdd(&g_count[i0], 1);
        atomicAdd(&g_count[i1], 1);
#pragma unroll
        for (int e = 0; e < NEXP; e++) logits_out[(size_t)t * NEXP + e] = acc[e];
    }
}

// ---------------- kernel 2: deterministic compaction ----------------
// one block per expert; token-order-preserving ballot scan
__global__ void compact_kernel() {
    int e = blockIdx.x;
    int tid = threadIdx.x;
    int lane = tid & 31;
    int w = tid >> 5;

    __shared__ int warp_sum[8];
    __shared__ int base_s;

    if (tid == 0) {
        int off = 0;
        for (int i = 0; i < e; i++) off += g_count[i];
        g_offset[e] = off;
        base_s = off;
    }
    __syncthreads();

    for (int t0 = 0; t0 < NTOK; t0 += 256) {
        int t = t0 + tid;
        int i0 = g_tok_idx[2*t];
        int i1 = g_tok_idx[2*t+1];
        bool f0 = (i0 == e);
        bool f  = f0 || (i1 == e);
        unsigned m = __ballot_sync(0xffffffffu, f);
        int pos = __popc(m & ((1u << lane) - 1u));
        if (lane == 31) warp_sum[w] = __popc(m);
        __syncthreads();
        int wbase = 0;
        for (int i = 0; i < w; i++) wbase += warp_sum[i];
        if (f) {
            int p = base_s + wbase + pos;
            g_list_token[p] = t;
            g_list_w[p] = f0 ? g_tok_w[2*t] : g_tok_w[2*t+1];
        }
        __syncthreads();
        if (tid == 0) {
            int tot = 0;
            for (int i = 0; i < 8; i++) tot += warp_sum[i];
            base_s += tot;
        }
        __syncthreads();
    }
}

// ---------------- GEMM tiling config ----------------
// block tile 128x128x16, 8 warps (2 M x 4 N), warp tile 64x32, mma m16n8k8 tf32
#define BM 128
#define BN 128
#define BK 16
#define AS_STR 20    // As[m][k] row stride (16 + 4 pad) -> conflict-free frag loads
#define BS_STR 136   // Bs[k][n] row stride (128 + 8 pad)

// ---------------- kernel 3: GEMM1  hmid = gelu(gather(X) @ W1[e]) ----------------
__global__ __launch_bounds__(256, 2)
void gemm1_kernel(const float* __restrict__ x, const float* __restrict__ w1) {
    int e = blockIdx.z;
    int cnt = g_count[e];
    int m0 = blockIdx.x * BM;
    if (m0 >= cnt) return;
    int off = g_offset[e];
    int n0 = blockIdx.y * BN;
    const float* W = w1 + (size_t)e * HID * DFF;

    __shared__ int toks[BM];
    __shared__ uint32_t As[2][BM][AS_STR];
    __shared__ uint32_t Bs[2][BK][BS_STR];

    int tid = threadIdx.x;
    if (tid < BM) {
        int r = m0 + tid;
        toks[tid] = g_list_token[off + min(r, cnt - 1)];
    }
    __syncthreads();

    // loader mapping
    int ar = tid >> 2;              // A row (first 64), +64 for second
    int ac = (tid & 3) * 4;         // A col within 16-k tile
    int brow = tid >> 5;            // B k-row (first 8), +8 for second
    int bcol = (tid & 31) * 4;      // B n-col
    size_t tA = (size_t)toks[ar];
    size_t tB = (size_t)toks[ar + 64];

    // prologue: stage 0
    float4 a0v = *reinterpret_cast<const float4*>(x + tA * HID + 0 + ac);
    float4 a1v = *reinterpret_cast<const float4*>(x + tB * HID + 0 + ac);
    float4 b0v = *reinterpret_cast<const float4*>(W + (size_t)(0 + brow) * DFF + n0 + bcol);
    float4 b1v = *reinterpret_cast<const float4*>(W + (size_t)(8 + brow) * DFF + n0 + bcol);
    As[0][ar][ac+0] = f2tf(a0v.x); As[0][ar][ac+1] = f2tf(a0v.y);
    As[0][ar][ac+2] = f2tf(a0v.z); As[0][ar][ac+3] = f2tf(a0v.w);
    As[0][ar+64][ac+0] = f2tf(a1v.x); As[0][ar+64][ac+1] = f2tf(a1v.y);
    As[0][ar+64][ac+2] = f2tf(a1v.z); As[0][ar+64][ac+3] = f2tf(a1v.w);
    Bs[0][brow][bcol+0] = f2tf(b0v.x); Bs[0][brow][bcol+1] = f2tf(b0v.y);
    Bs[0][brow][bcol+2] = f2tf(b0v.z); Bs[0][brow][bcol+3] = f2tf(b0v.w);
    Bs[0][brow+8][bcol+0] = f2tf(b1v.x); Bs[0][brow+8][bcol+1] = f2tf(b1v.y);
    Bs[0][brow+8][bcol+2] = f2tf(b1v.z); Bs[0][brow+8][bcol+3] = f2tf(b1v.w);
    __syncthreads();

    int lane = tid & 31;
    int gid = lane >> 2, t4 = lane & 3;
    int w = tid >> 5;
    int wm = (w & 1) * 64;
    int wn = (w >> 1) * 32;

    float c[4][4][4];
#pragma unroll
    for (int mt = 0; mt < 4; mt++)
#pragma unroll
        for (int nt = 0; nt < 4; nt++)
#pragma unroll
            for (int i = 0; i < 4; i++) c[mt][nt][i] = 0.f;

    const int KT = HID / BK;   // 128
    for (int kt = 0; kt < KT; kt++) {
        int buf = kt & 1;
        if (kt + 1 < KT) {
            int k0 = (kt + 1) * BK;
            a0v = *reinterpret_cast<const float4*>(x + tA * HID + k0 + ac);
            a1v = *reinterpret_cast<const float4*>(x + tB * HID + k0 + ac);
            b0v = *reinterpret_cast<const float4*>(W + (size_t)(k0 + brow) * DFF + n0 + bcol);
            b1v = *reinterpret_cast<const float4*>(W + (size_t)(k0 + 8 + brow) * DFF + n0 + bcol);
        }
#pragma unroll
        for (int ks = 0; ks < BK; ks += 8) {
            uint32_t a[4][4], b[4][2];
#pragma unroll
            for (int mt = 0; mt < 4; mt++) {
                int m = wm + mt * 16;
                a[mt][0] = As[buf][m + gid    ][ks + t4];
                a[mt][1] = As[buf][m + gid + 8][ks + t4];
                a[mt][2] = As[buf][m + gid    ][ks + t4 + 4];
                a[mt][3] = As[buf][m + gid + 8][ks + t4 + 4];
            }
#pragma unroll
            for (int nt = 0; nt < 4; nt++) {
                int n = wn + nt * 8;
                b[nt][0] = Bs[buf][ks + t4    ][n + gid];
                b[nt][1] = Bs[buf][ks + t4 + 4][n + gid];
            }
#pragma unroll
            for (int mt = 0; mt < 4; mt++)
#pragma unroll
                for (int nt = 0; nt < 4; nt++)
                    mma_tf32(c[mt][nt], a[mt][0], a[mt][1], a[mt][2], a[mt][3],
                             b[nt][0], b[nt][1]);
        }
        if (kt + 1 < KT) {
            int nb = buf ^ 1;
            As[nb][ar][ac+0] = f2tf(a0v.x); As[nb][ar][ac+1] = f2tf(a0v.y);
            As[nb][ar][ac+2] = f2tf(a0v.z); As[nb][ar][ac+3] = f2tf(a0v.w);
            As[nb][ar+64][ac+0] = f2tf(a1v.x); As[nb][ar+64][ac+1] = f2tf(a1v.y);
            As[nb][ar+64][ac+2] = f2tf(a1v.z); As[nb][ar+64][ac+3] = f2tf(a1v.w);
            Bs[nb][brow][bcol+0] = f2tf(b0v.x); Bs[nb][brow][bcol+1] = f2tf(b0v.y);
            Bs[nb][brow][bcol+2] = f2tf(b0v.z); Bs[nb][brow][bcol+3] = f2tf(b0v.w);
            Bs[nb][brow+8][bcol+0] = f2tf(b1v.x); Bs[nb][brow+8][bcol+1] = f2tf(b1v.y);
            Bs[nb][brow+8][bcol+2] = f2tf(b1v.z); Bs[nb][brow+8][bcol+3] = f2tf(b1v.w);
        }
        __syncthreads();
    }

    // epilogue: gelu + store to hmid scratch
#pragma unroll
    for (int mt = 0; mt < 4; mt++)
#pragma unroll
        for (int nt = 0; nt < 4; nt++) {
            int col = n0 + wn + nt * 8 + t4 * 2;
#pragma unroll
            for (int h = 0; h < 2; h++) {
                int row = wm + mt * 16 + gid + h * 8;
                int gr = m0 + row;
                if (gr < cnt) {
                    float2 v;
                    v.x = gelu_f(c[mt][nt][h * 2 + 0]);
                    v.y = gelu_f(c[mt][nt][h * 2 + 1]);
                    *reinterpret_cast<float2*>(&g_hmid[(size_t)(off + gr) * DFF + col]) = v;
                }
            }
        }
}

// ---------------- kernel 4: GEMM2  out += w * (hmid @ W2[e]) ----------------
__global__ __launch_bounds__(256, 2)
void gemm2_kernel(const float* __restrict__ w2, float* __restrict__ out) {
    int e = blockIdx.z;
    int cnt = g_count[e];
    int m0 = blockIdx.x * BM;
    if (m0 >= cnt) return;
    int off = g_offset[e];
    int n0 = blockIdx.y * BN;
    const float* W = w2 + (size_t)e * DFF * HID;

    __shared__ int   toks[BM];
    __shared__ float wts[BM];
    __shared__ uint32_t As[2][BM][AS_STR];
    __shared__ uint32_t Bs[2][BK][BS_STR];

    int tid = threadIdx.x;
    if (tid < BM) {
        int r = m0 + tid;
        int rc = min(r, cnt - 1);
        toks[tid] = g_list_token[off + rc];
        wts[tid]  = g_list_w[off + rc];
    }

    int ar = tid >> 2;
    int ac = (tid & 3) * 4;
    int brow = tid >> 5;
    int bcol = (tid & 31) * 4;
    const float* arowA = g_hmid + (size_t)(off + min(m0 + ar,      cnt - 1)) * DFF;
    const float* arowB = g_hmid + (size_t)(off + min(m0 + ar + 64, cnt - 1)) * DFF;

    float4 a0v = *reinterpret_cast<const float4*>(arowA + 0 + ac);
    float4 a1v = *reinterpret_cast<const float4*>(arowB + 0 + ac);
    float4 b0v = *reinterpret_cast<const float4*>(W + (size_t)(0 + brow) * HID + n0 + bcol);
    float4 b1v = *reinterpret_cast<const float4*>(W + (size_t)(8 + brow) * HID + n0 + bcol);
    As[0][ar][ac+0] = f2tf(a0v.x); As[0][ar][ac+1] = f2tf(a0v.y);
    As[0][ar][ac+2] = f2tf(a0v.z); As[0][ar][ac+3] = f2tf(a0v.w);
    As[0][ar+64][ac+0] = f2tf(a1v.x); As[0][ar+64][ac+1] = f2tf(a1v.y);
    As[0][ar+64][ac+2] = f2tf(a1v.z); As[0][ar+64][ac+3] = f2tf(a1v.w);
    Bs[0][brow][bcol+0] = f2tf(b0v.x); Bs[0][brow][bcol+1] = f2tf(b0v.y);
    Bs[0][brow][bcol+2] = f2tf(b0v.z); Bs[0][brow][bcol+3] = f2tf(b0v.w);
    Bs[0][brow+8][bcol+0] = f2tf(b1v.x); Bs[0][brow+8][bcol+1] = f2tf(b1v.y);
    Bs[0][brow+8][bcol+2] = f2tf(b1v.z); Bs[0][brow+8][bcol+3] = f2tf(b1v.w);
    __syncthreads();

    int lane = tid & 31;
    int gid = lane >> 2, t4 = lane & 3;
    int w = tid >> 5;
    int wm = (w & 1) * 64;
    int wn = (w >> 1) * 32;

    float c[4][4][4];
#pragma unroll
    for (int mt = 0; mt < 4; mt++)
#pragma unroll
        for (int nt = 0; nt < 4; nt++)
#pragma unroll
            for (int i = 0; i < 4; i++) c[mt][nt][i] = 0.f;

    const int KT = DFF / BK;   // 512
    for (int kt = 0; kt < KT; kt++) {
        int buf = kt & 1;
        if (kt + 1 < KT) {
            int k0 = (kt + 1) * BK;
            a0v = *reinterpret_cast<const float4*>(arowA + k0 + ac);
            a1v = *reinterpret_cast<const float4*>(arowB + k0 + ac);
            b0v = *reinterpret_cast<const float4*>(W + (size_t)(k0 + brow) * HID + n0 + bcol);
            b1v = *reinterpret_cast<const float4*>(W + (size_t)(k0 + 8 + brow) * HID + n0 + bcol);
        }
#pragma unroll
        for (int ks = 0; ks < BK; ks += 8) {
            uint32_t a[4][4], b[4][2];
#pragma unroll
            for (int mt = 0; mt < 4; mt++) {
                int m = wm + mt * 16;
                a[mt][0] = As[buf][m + gid    ][ks + t4];
                a[mt][1] = As[buf][m + gid + 8][ks + t4];
                a[mt][2] = As[buf][m + gid    ][ks + t4 + 4];
                a[mt][3] = As[buf][m + gid + 8][ks + t4 + 4];
            }
#pragma unroll
            for (int nt = 0; nt < 4; nt++) {
                int n = wn + nt * 8;
                b[nt][0] = Bs[buf][ks + t4    ][n + gid];
                b[nt][1] = Bs[buf][ks + t4 + 4][n + gid];
            }
#pragma unroll
            for (int mt = 0; mt < 4; mt++)
#pragma unroll
                for (int nt = 0; nt < 4; nt++)
                    mma_tf32(c[mt][nt], a[mt][0], a[mt][1], a[mt][2], a[mt][3],
                             b[nt][0], b[nt][1]);
        }
        if (kt + 1 < KT) {
            int nb = buf ^ 1;
            As[nb][ar][ac+0] = f2tf(a0v.x); As[nb][ar][ac+1] = f2tf(a0v.y);
            As[nb][ar][ac+2] = f2tf(a0v.z); As[nb][ar][ac+3] = f2tf(a0v.w);
            As[nb][ar+64][ac+0] = f2tf(a1v.x); As[nb][ar+64][ac+1] = f2tf(a1v.y);
            As[nb][ar+64][ac+2] = f2tf(a1v.z); As[nb][ar+64][ac+3] = f2tf(a1v.w);
            Bs[nb][brow][bcol+0] = f2tf(b0v.x); Bs[nb][brow][bcol+1] = f2tf(b0v.y);
            Bs[nb][brow][bcol+2] = f2tf(b0v.z); Bs[nb][brow][bcol+3] = f2tf(b0v.w);
            Bs[nb][brow+8][bcol+0] = f2tf(b1v.x); Bs[nb][brow+8][bcol+1] = f2tf(b1v.y);
            Bs[nb][brow+8][bcol+2] = f2tf(b1v.z); Bs[nb][brow+8][bcol+3] = f2tf(b1v.w);
        }
        __syncthreads();
    }

    // epilogue: weighted atomic scatter into out
#pragma unroll
    for (int mt = 0; mt < 4; mt++)
#pragma unroll
        for (int nt = 0; nt < 4; nt++) {
            int col = n0 + wn + nt * 8 + t4 * 2;
#pragma unroll
            for (int h = 0; h < 2; h++) {
                int row = wm + mt * 16 + gid + h * 8;
                int gr = m0 + row;
                if (gr < cnt) {
                    int tok = toks[row];
                    float wt = wts[row];
                    float* o = out + (size_t)tok * HID + col;
                    atomicAdd(o + 0, wt * c[mt][nt][h * 2 + 0]);
                    atomicAdd(o + 1, wt * c[mt][nt][h * 2 + 1]);
                }
            }
        }
}

// ---------------- launch ----------------
extern "C" void kernel_launch(void* const* d_in, const int* in_sizes, int n_in,
                              void* d_out, int out_size) {
    const float* x  = (const float*)d_in[0];   // [B,S,H] fp32
    const float* wg = (const float*)d_in[1];   // [H,E]
    const float* w1 = (const float*)d_in[2];   // [E,H,DFF]
    const float* w2 = (const float*)d_in[3];   // [E,DFF,H]
    float* out    = (float*)d_out;                      // [T,H] first
    float* logits = out + (size_t)NTOK * HID;           // [T,E] second

    init_kernel<<<2048, 256>>>(out);
    router_kernel<<<NTOK / 8, 256>>>(x, wg, logits);
    compact_kernel<<<NEXP, 256>>>();
    gemm1_kernel<<<dim3(NTOK / BM, DFF / BN, NEXP), 256>>>(x, w1);
    gemm2_kernel<<<dim3(NTOK / BM, HID / BN, NEXP), 256>>>(w2, out);
}

// round 3
// speedup vs baseline: 1.0010x; 1.0010x over previous
#include <cuda_runtime.h>
#include <cuda_bf16.h>
#include <cstdint>
#include <math.h>

// ---------------- problem constants ----------------
#define HID  2048
#define DFF  8192
#define NEXP 8
#define NTOK 8192            // B*S = 4*2048
#define SLOTS (2*NTOK)       // top-2 => 16384 token-expert slots

// ---------------- device scratch (no allocs allowed) ----------------
__device__ int   g_count[NEXP];
__device__ int   g_offset[NEXP];
__device__ int   g_tok_idx[2*NTOK];     // per-token top2 expert ids
__device__ float g_tok_w[2*NTOK];       // per-token top2 weights
__device__ int   g_list_token[SLOTS];   // compacted per-expert token lists
__device__ float g_list_w[SLOTS];
__device__ float g_hmid[(size_t)SLOTS * DFF];   // 512 MB fp32 intermediate

// ---------------- helpers ----------------
__device__ __forceinline__ uint32_t f2tf(float f) {
    uint32_t r;
    asm("cvt.rna.tf32.f32 %0, %1;" : "=r"(r) : "f"(f));
    return r;
}

__device__ __forceinline__ void mma_tf32(float c[4],
                                         uint32_t a0, uint32_t a1, uint32_t a2, uint32_t a3,
                                         uint32_t b0, uint32_t b1) {
    asm volatile(
        "mma.sync.aligned.m16n8k8.row.col.f32.tf32.tf32.f32 "
        "{%0,%1,%2,%3}, {%4,%5,%6,%7}, {%8,%9}, {%0,%1,%2,%3};\n"
        : "+f"(c[0]), "+f"(c[1]), "+f"(c[2]), "+f"(c[3])
        : "r"(a0), "r"(a1), "r"(a2), "r"(a3), "r"(b0), "r"(b1));
}

__device__ __forceinline__ float gelu_f(float v) {
    // jax.nn.gelu approximate=True (tanh form)
    float v3 = v * v * v;
    return 0.5f * v * (1.0f + tanhf(0.7978845608028654f * (v + 0.044715f * v3)));
}

// ---------------- kernel 0: init ----------------
__global__ void init_kernel(float* __restrict__ out) {
    size_t n4 = (size_t)NTOK * HID / 4;
    size_t stride = (size_t)gridDim.x * blockDim.x;
    float4 z = make_float4(0.f, 0.f, 0.f, 0.f);
    for (size_t i = (size_t)blockIdx.x * blockDim.x + threadIdx.x; i < n4; i += stride)
        reinterpret_cast<float4*>(out)[i] = z;
    if (blockIdx.x == 0 && threadIdx.x < NEXP) g_count[threadIdx.x] = 0;
}

// ---------------- kernel 1: router ----------------
// one warp per token: logits = x[t] @ w_gate, softmax fp32, top-2
__global__ void router_kernel(const float* __restrict__ x,
                              const float* __restrict__ wg,
                              float* __restrict__ logits_out) {
    int warp = threadIdx.x >> 5;
    int lane = threadIdx.x & 31;
    int t = blockIdx.x * 8 + warp;
    if (t >= NTOK) return;

    const float* xr = x + (size_t)t * HID;
    float acc[NEXP];
#pragma unroll
    for (int e = 0; e < NEXP; e++) acc[e] = 0.f;

    for (int h = lane; h < HID; h += 32) {
        float xv = xr[h];
        float4 g0 = *reinterpret_cast<const float4*>(wg + (size_t)h * NEXP);
        float4 g1 = *reinterpret_cast<const float4*>(wg + (size_t)h * NEXP + 4);
        acc[0] += xv * g0.x; acc[1] += xv * g0.y; acc[2] += xv * g0.z; acc[3] += xv * g0.w;
        acc[4] += xv * g1.x; acc[5] += xv * g1.y; acc[6] += xv * g1.z; acc[7] += xv * g1.w;
    }
#pragma unroll
    for (int e = 0; e < NEXP; e++)
#pragma unroll
        for (int s = 16; s > 0; s >>= 1)
            acc[e] += __shfl_xor_sync(0xffffffffu, acc[e], s);

    if (lane == 0) {
        float mx = acc[0];
#pragma unroll
        for (int e = 1; e < NEXP; e++) mx = fmaxf(mx, acc[e]);
        float p[NEXP];
        float s = 0.f;
#pragma unroll
        for (int e = 0; e < NEXP; e++) { p[e] = expf(acc[e] - mx); s += p[e]; }
        float inv = 1.f / s;
#pragma unroll
        for (int e = 0; e < NEXP; e++) p[e] *= inv;

        int i0 = 0;
#pragma unroll
        for (int e = 1; e < NEXP; e++) if (p[e] > p[i0]) i0 = e;
        int i1 = (i0 == 0) ? 1 : 0;
#pragma unroll
        for (int e = 0; e < NEXP; e++) if (e != i0 && p[e] > p[i1]) i1 = e;

        g_tok_idx[2*t+0] = i0; g_tok_idx[2*t+1] = i1;
        g_tok_w[2*t+0] = p[i0]; g_tok_w[2*t+1] = p[i1];
        atomicAdd(&g_count[i0], 1);
        atomicAdd(&g_count[i1], 1);
#pragma unroll
        for (int e = 0; e < NEXP; e++) logits_out[(size_t)t * NEXP + e] = acc[e];
    }
}

// ---------------- kernel 2: deterministic compaction ----------------
// one block per expert; token-order-preserving ballot scan
__global__ void compact_kernel() {
    int e = blockIdx.x;
    int tid = threadIdx.x;
    int lane = tid & 31;
    int w = tid >> 5;

    __shared__ int warp_sum[8];
    __shared__ int base_s;

    if (tid == 0) {
        int off = 0;
        for (int i = 0; i < e; i++) off += g_count[i];
        g_offset[e] = off;
        base_s = off;
    }
    __syncthreads();

    for (int t0 = 0; t0 < NTOK; t0 += 256) {
        int t = t0 + tid;
        int i0 = g_tok_idx[2*t];
        int i1 = g_tok_idx[2*t+1];
        bool f0 = (i0 == e);
        bool f  = f0 || (i1 == e);
        unsigned m = __ballot_sync(0xffffffffu, f);
        int pos = __popc(m & ((1u << lane) - 1u));
        if (lane == 31) warp_sum[w] = __popc(m);
        __syncthreads();
        int wbase = 0;
        for (int i = 0; i < w; i++) wbase += warp_sum[i];
        if (f) {
            int p = base_s + wbase + pos;
            g_list_token[p] = t;
            g_list_w[p] = f0 ? g_tok_w[2*t] : g_tok_w[2*t+1];
        }
        __syncthreads();
        if (tid == 0) {
            int tot = 0;
            for (int i = 0; i < 8; i++) tot += warp_sum[i];
            base_s += tot;
        }
        __syncthreads();
    }
}

// ---------------- GEMM tiling config ----------------
// block tile 128x128x16, 8 warps (2 M x 4 N), warp tile 64x32, mma m16n8k8 tf32
#define BM 128
#define BN 128
#define BK 16
#define AS_STR 20    // As[m][k] row stride (16 + 4 pad) -> conflict-free frag loads
#define BS_STR 136   // Bs[k][n] row stride (128 + 8 pad)

// ---------------- kernel 3: GEMM1  hmid = gelu(gather(X) @ W1[e]) ----------------
__global__ __launch_bounds__(256, 2)
void gemm1_kernel(const float* __restrict__ x, const float* __restrict__ w1) {
    int e = blockIdx.z;
    int cnt = g_count[e];
    int m0 = blockIdx.x * BM;
    if (m0 >= cnt) return;
    int off = g_offset[e];
    int n0 = blockIdx.y * BN;
    const float* W = w1 + (size_t)e * HID * DFF;

    __shared__ int toks[BM];
    __shared__ uint32_t As[2][BM][AS_STR];
    __shared__ uint32_t Bs[2][BK][BS_STR];

    int tid = threadIdx.x;
    if (tid < BM) {
        int r = m0 + tid;
        toks[tid] = g_list_token[off + min(r, cnt - 1)];
    }
    __syncthreads();

    // loader mapping
    int ar = tid >> 2;              // A row (first 64), +64 for second
    int ac = (tid & 3) * 4;         // A col within 16-k tile
    int brow = tid >> 5;            // B k-row (first 8), +8 for second
    int bcol = (tid & 31) * 4;      // B n-col
    size_t tA = (size_t)toks[ar];
    size_t tB = (size_t)toks[ar + 64];

    // prologue: stage 0
    float4 a0v = *reinterpret_cast<const float4*>(x + tA * HID + 0 + ac);
    float4 a1v = *reinterpret_cast<const float4*>(x + tB * HID + 0 + ac);
    float4 b0v = *reinterpret_cast<const float4*>(W + (size_t)(0 + brow) * DFF + n0 + bcol);
    float4 b1v = *reinterpret_cast<const float4*>(W + (size_t)(8 + brow) * DFF + n0 + bcol);
    As[0][ar][ac+0] = f2tf(a0v.x); As[0][ar][ac+1] = f2tf(a0v.y);
    As[0][ar][ac+2] = f2tf(a0v.z); As[0][ar][ac+3] = f2tf(a0v.w);
    As[0][ar+64][ac+0] = f2tf(a1v.x); As[0][ar+64][ac+1] = f2tf(a1v.y);
    As[0][ar+64][ac+2] = f2tf(a1v.z); As[0][ar+64][ac+3] = f2tf(a1v.w);
    Bs[0][brow][bcol+0] = f2tf(b0v.x); Bs[0][brow][bcol+1] = f2tf(b0v.y);
    Bs[0][brow][bcol+2] = f2tf(b0v.z); Bs[0][brow][bcol+3] = f2tf(b0v.w);
    Bs[0][brow+8][bcol+0] = f2tf(b1v.x); Bs[0][brow+8][bcol+1] = f2tf(b1v.y);
    Bs[0][brow+8][bcol+2] = f2tf(b1v.z); Bs[0][brow+8][bcol+3] = f2tf(b1v.w);
    __syncthreads();

    int lane = tid & 31;
    int gid = lane >> 2, t4 = lane & 3;
    int w = tid >> 5;
    int wm = (w & 1) * 64;
    int wn = (w >> 1) * 32;

    float c[4][4][4];
#pragma unroll
    for (int mt = 0; mt < 4; mt++)
#pragma unroll
        for (int nt = 0; nt < 4; nt++)
#pragma unroll
            for (int i = 0; i < 4; i++) c[mt][nt][i] = 0.f;

    const int KT = HID / BK;   // 128
    for (int kt = 0; kt < KT; kt++) {
        int buf = kt & 1;
        if (kt + 1 < KT) {
            int k0 = (kt + 1) * BK;
            a0v = *reinterpret_cast<const float4*>(x + tA * HID + k0 + ac);
            a1v = *reinterpret_cast<const float4*>(x + tB * HID + k0 + ac);
            b0v = *reinterpret_cast<const float4*>(W + (size_t)(k0 + brow) * DFF + n0 + bcol);
            b1v = *reinterpret_cast<const float4*>(W + (size_t)(k0 + 8 + brow) * DFF + n0 + bcol);
        }
#pragma unroll
        for (int ks = 0; ks < BK; ks += 8) {
            uint32_t a[4][4], b[4][2];
#pragma unroll
            for (int mt = 0; mt < 4; mt++) {
                int m = wm + mt * 16;
                a[mt][0] = As[buf][m + gid    ][ks + t4];
                a[mt][1] = As[buf][m + gid + 8][ks + t4];
                a[mt][2] = As[buf][m + gid    ][ks + t4 + 4];
                a[mt][3] = As[buf][m + gid + 8][ks + t4 + 4];
            }
#pragma unroll
            for (int nt = 0; nt < 4; nt++) {
                int n = wn + nt * 8;
                b[nt][0] = Bs[buf][ks + t4    ][n + gid];
                b[nt][1] = Bs[buf][ks + t4 + 4][n + gid];
            }
#pragma unroll
            for (int mt = 0; mt < 4; mt++)
#pragma unroll
                for (int nt = 0; nt < 4; nt++)
                    mma_tf32(c[mt][nt], a[mt][0], a[mt][1], a[mt][2], a[mt][3],
                             b[nt][0], b[nt][1]);
        }
        if (kt + 1 < KT) {
            int nb = buf ^ 1;
            As[nb][ar][ac+0] = f2tf(a0v.x); As[nb][ar][ac+1] = f2tf(a0v.y);
            As[nb][ar][ac+2] = f2tf(a0v.z); As[nb][ar][ac+3] = f2tf(a0v.w);
            As[nb][ar+64][ac+0] = f2tf(a1v.x); As[nb][ar+64][ac+1] = f2tf(a1v.y);
            As[nb][ar+64][ac+2] = f2tf(a1v.z); As[nb][ar+64][ac+3] = f2tf(a1v.w);
            Bs[nb][brow][bcol+0] = f2tf(b0v.x); Bs[nb][brow][bcol+1] = f2tf(b0v.y);
            Bs[nb][brow][bcol+2] = f2tf(b0v.z); Bs[nb][brow][bcol+3] = f2tf(b0v.w);
            Bs[nb][brow+8][bcol+0] = f2tf(b1v.x); Bs[nb][brow+8][bcol+1] = f2tf(b1v.y);
            Bs[nb][brow+8][bcol+2] = f2tf(b1v.z); Bs[nb][brow+8][bcol+3] = f2tf(b1v.w);
        }
        __syncthreads();
    }

    // epilogue: gelu + store to hmid scratch
#pragma unroll
    for (int mt = 0; mt < 4; mt++)
#pragma unroll
        for (int nt = 0; nt < 4; nt++) {
            int col = n0 + wn + nt * 8 + t4 * 2;
#pragma unroll
            for (int h = 0; h < 2; h++) {
                int row = wm + mt * 16 + gid + h * 8;
                int gr = m0 + row;
                if (gr < cnt) {
                    float2 v;
                    v.x = gelu_f(c[mt][nt][h * 2 + 0]);
                    v.y = gelu_f(c[mt][nt][h * 2 + 1]);
                    *reinterpret_cast<float2*>(&g_hmid[(size_t)(off + gr) * DFF + col]) = v;
                }
            }
        }
}

// ---------------- kernel 4: GEMM2  out += w * (hmid @ W2[e]) ----------------
__global__ __launch_bounds__(256, 2)
void gemm2_kernel(const float* __restrict__ w2, float* __restrict__ out) {
    int e = blockIdx.z;
    int cnt = g_count[e];
    int m0 = blockIdx.x * BM;
    if (m0 >= cnt) return;
    int off = g_offset[e];
    int n0 = blockIdx.y * BN;
    const float* W = w2 + (size_t)e * DFF * HID;

    __shared__ int   toks[BM];
    __shared__ float wts[BM];
    __shared__ uint32_t As[2][BM][AS_STR];
    __shared__ uint32_t Bs[2][BK][BS_STR];

    int tid = threadIdx.x;
    if (tid < BM) {
        int r = m0 + tid;
        int rc = min(r, cnt - 1);
        toks[tid] = g_list_token[off + rc];
        wts[tid]  = g_list_w[off + rc];
    }

    int ar = tid >> 2;
    int ac = (tid & 3) * 4;
    int brow = tid >> 5;
    int bcol = (tid & 31) * 4;
    const float* arowA = g_hmid + (size_t)(off + min(m0 + ar,      cnt - 1)) * DFF;
    const float* arowB = g_hmid + (size_t)(off + min(m0 + ar + 64, cnt - 1)) * DFF;

    float4 a0v = *reinterpret_cast<const float4*>(arowA + 0 + ac);
    float4 a1v = *reinterpret_cast<const float4*>(arowB + 0 + ac);
    float4 b0v = *reinterpret_cast<const float4*>(W + (size_t)(0 + brow) * HID + n0 + bcol);
    float4 b1v = *reinterpret_cast<const float4*>(W + (size_t)(8 + brow) * HID + n0 + bcol);
    As[0][ar][ac+0] = f2tf(a0v.x); As[0][ar][ac+1] = f2tf(a0v.y);
    As[0][ar][ac+2] = f2tf(a0v.z); As[0][ar][ac+3] = f2tf(a0v.w);
    As[0][ar+64][ac+0] = f2tf(a1v.x); As[0][ar+64][ac+1] = f2tf(a1v.y);
    As[0][ar+64][ac+2] = f2tf(a1v.z); As[0][ar+64][ac+3] = f2tf(a1v.w);
    Bs[0][brow][bcol+0] = f2tf(b0v.x); Bs[0][brow][bcol+1] = f2tf(b0v.y);
    Bs[0][brow][bcol+2] = f2tf(b0v.z); Bs[0][brow][bcol+3] = f2tf(b0v.w);
    Bs[0][brow+8][bcol+0] = f2tf(b1v.x); Bs[0][brow+8][bcol+1] = f2tf(b1v.y);
    Bs[0][brow+8][bcol+2] = f2tf(b1v.z); Bs[0][brow+8][bcol+3] = f2tf(b1v.w);
    __syncthreads();

    int lane = tid & 31;
    int gid = lane >> 2, t4 = lane & 3;
    int w = tid >> 5;
    int wm = (w & 1) * 64;
    int wn = (w >> 1) * 32;

    float c[4][4][4];
#pragma unroll
    for (int mt = 0; mt < 4; mt++)
#pragma unroll
        for (int nt = 0; nt < 4; nt++)
#pragma unroll
            for (int i = 0; i < 4; i++) c[mt][nt][i] = 0.f;

    const int KT = DFF / BK;   // 512
    for (int kt = 0; kt < KT; kt++) {
        int buf = kt & 1;
        if (kt + 1 < KT) {
            int k0 = (kt + 1) * BK;
            a0v = *reinterpret_cast<const float4*>(arowA + k0 + ac);
            a1v = *reinterpret_cast<const float4*>(arowB + k0 + ac);
            b0v = *reinterpret_cast<const float4*>(W + (size_t)(k0 + brow) * HID + n0 + bcol);
            b1v = *reinterpret_cast<const float4*>(W + (size_t)(k0 + 8 + brow) * HID + n0 + bcol);
        }
#pragma unroll
        for (int ks = 0; ks < BK; ks += 8) {
            uint32_t a[4][4], b[4][2];
#pragma unroll
            for (int mt = 0; mt < 4; mt++) {
                int m = wm + mt * 16;
                a[mt][0] = As[buf][m + gid    ][ks + t4];
                a[mt][1] = As[buf][m + gid + 8][ks + t4];
                a[mt][2] = As[buf][m + gid    ][ks + t4 + 4];
                a[mt][3] = As[buf][m + gid + 8][ks + t4 + 4];
            }
#pragma unroll
            for (int nt = 0; nt < 4; nt++) {
                int n = wn + nt * 8;
                b[nt][0] = Bs[buf][ks + t4    ][n + gid];
                b[nt][1] = Bs[buf][ks + t4 + 4][n + gid];
            }
#pragma unroll
            for (int mt = 0; mt < 4; mt++)
#pragma unroll
                for (int nt = 0; nt < 4; nt++)
                    mma_tf32(c[mt][nt], a[mt][0], a[mt][1], a[mt][2], a[mt][3],
                             b[nt][0], b[nt][1]);
        }
        if (kt + 1 < KT) {
            int nb = buf ^ 1;
            As[nb][ar][ac+0] = f2tf(a0v.x); As[nb][ar][ac+1] = f2tf(a0v.y);
            As[nb][ar][ac+2] = f2tf(a0v.z); As[nb][ar][ac+3] = f2tf(a0v.w);
            As[nb][ar+64][ac+0] = f2tf(a1v.x); As[nb][ar+64][ac+1] = f2tf(a1v.y);
            As[nb][ar+64][ac+2] = f2tf(a1v.z); As[nb][ar+64][ac+3] = f2tf(a1v.w);
            Bs[nb][brow][bcol+0] = f2tf(b0v.x); Bs[nb][brow][bcol+1] = f2tf(b0v.y);
            Bs[nb][brow][bcol+2] = f2tf(b0v.z); Bs[nb][brow][bcol+3] = f2tf(b0v.w);
            Bs[nb][brow+8][bcol+0] = f2tf(b1v.x); Bs[nb][brow+8][bcol+1] = f2tf(b1v.y);
            Bs[nb][brow+8][bcol+2] = f2tf(b1v.z); Bs[nb][brow+8][bcol+3] = f2tf(b1v.w);
        }
        __syncthreads();
    }

    // epilogue: weighted atomic scatter into out
#pragma unroll
    for (int mt = 0; mt < 4; mt++)
#pragma unroll
        for (int nt = 0; nt < 4; nt++) {
            int col = n0 + wn + nt * 8 + t4 * 2;
#pragma unroll
            for (int h = 0; h < 2; h++) {
                int row = wm + mt * 16 + gid + h * 8;
                int gr = m0 + row;
                if (gr < cnt) {
                    int tok = toks[row];
                    float wt = wts[row];
                    float* o = out + (size_t)tok * HID + col;
                    atomicAdd(o + 0, wt * c[mt][nt][h * 2 + 0]);
                    atomicAdd(o + 1, wt * c[mt][nt][h * 2 + 1]);
                }
            }
        }
}

// ---------------- launch ----------------
extern "C" void kernel_launch(void* const* d_in, const int* in_sizes, int n_in,
                              void* d_out, int out_size) {
    const float* x  = (const float*)d_in[0];   // [B,S,H] fp32
    const float* wg = (const float*)d_in[1];   // [H,E]
    const float* w1 = (const float*)d_in[2];   // [E,H,DFF]
    const float* w2 = (const float*)d_in[3];   // [E,DFF,H]
    float* out    = (float*)d_out;                      // [T,H] first
    float* logits = out + (size_t)NTOK * HID;           // [T,E] second

    init_kernel<<<2048, 256>>>(out);
    router_kernel<<<NTOK / 8, 256>>>(x, wg, logits);
    compact_kernel<<<NEXP, 256>>>();
    gemm1_kernel<<<dim3(NTOK / BM, DFF / BN, NEXP), 256>>>(x, w1);
    gemm2_kernel<<<dim3(NTOK / BM, HID / BN, NEXP), 256>>>(w2, out);
}